// round 2
// baseline (speedup 1.0000x reference)
#include <cuda_runtime.h>

#define N_NODES 100000
#define N_EDGES 1600000
#define IN_DIM 128
#define HID_DIM 128
#define OUT_DIM 64

// ---------------- device scratch (allocation-free rule: __device__ globals) ----
__device__ float g_deg[N_NODES];
__device__ float g_dis[N_NODES];
__device__ float g_h1[(size_t)N_NODES * HID_DIM];    // x @ W1
__device__ float g_agg1[(size_t)N_NODES * HID_DIM];  // scatter target (+b1)
__device__ float g_h2[(size_t)N_NODES * OUT_DIM];    // relu(agg1) @ W2

// ---------------- vector reductions (sm_90+) ----------------------------------
__device__ __forceinline__ void red_add_v4(float* addr, float4 v) {
    asm volatile("red.global.add.v4.f32 [%0], {%1, %2, %3, %4};"
                 :: "l"(addr), "f"(v.x), "f"(v.y), "f"(v.z), "f"(v.w) : "memory");
}
__device__ __forceinline__ void red_add_v2(float* addr, float2 v) {
    asm volatile("red.global.add.v2.f32 [%0], {%1, %2};"
                 :: "l"(addr), "f"(v.x), "f"(v.y) : "memory");
}

// ---------------- small utility kernels ----------------------------------------
__global__ void zero_deg_kernel(float* deg) {
    int i = blockIdx.x * blockDim.x + threadIdx.x;
    if (i < N_NODES) deg[i] = 0.0f;
}

__global__ void deg_kernel(const int* __restrict__ dst, float* __restrict__ deg) {
    int i = blockIdx.x * blockDim.x + threadIdx.x;
    if (i < N_EDGES) atomicAdd(&deg[dst[i]], 1.0f);
}

__global__ void dis_kernel(const float* __restrict__ deg, float* __restrict__ dis) {
    int i = blockIdx.x * blockDim.x + threadIdx.x;
    if (i < N_NODES) {
        float d = deg[i];
        dis[i] = (d > 0.0f) ? rsqrtf(d) : 0.0f;
    }
}

// out (flattened [rows, ncols4*4]) initialized so every row == bias vector.
template<int NCOLS4>
__global__ void init_bias_kernel(float4* __restrict__ out, const float* __restrict__ b,
                                 long long total4) {
    long long i = (long long)blockIdx.x * blockDim.x + threadIdx.x;
    long long stride = (long long)gridDim.x * blockDim.x;
    for (; i < total4; i += stride) {
        int c = (int)(i & (NCOLS4 - 1));
        out[i] = ((const float4*)b)[c];
    }
}

// ---------------- SGEMM: C[M,BN] = op(A[M,128]) @ B[128,BN] -------------------
// BM=128, BK=16, 256 threads. TN in {8,4} gives BN in {128,64}.
template<int BN, int TN, bool RELU_A>
__global__ void __launch_bounds__(256) gemm128_kernel(const float* __restrict__ A,
                                                      const float* __restrict__ B,
                                                      float* __restrict__ C, int M) {
    constexpr int BM = 128;
    constexpr int BK = 16;
    __shared__ float As[BK][BM];   // transposed A tile: As[k][m]
    __shared__ float Bs[BK][BN];

    const int tid = threadIdx.x;
    const int m0 = blockIdx.x * BM;

    const int tx = tid & 15;         // 16 col-groups
    const int ty = tid >> 4;         // 16 row-groups
    const int row = ty * 8;
    const int col = tx * TN;

    float acc[8][TN];
#pragma unroll
    for (int i = 0; i < 8; i++)
#pragma unroll
        for (int j = 0; j < TN; j++) acc[i][j] = 0.0f;

    for (int kt = 0; kt < 128; kt += BK) {
        __syncthreads();
        // ---- load A tile (transpose into As[k][m]); 512 float4, 2 per thread
#pragma unroll
        for (int it = 0; it < 2; it++) {
            int idx = tid + it * 256;        // 0..511
            int r   = idx >> 2;              // 0..127
            int cg  = idx & 3;               // float4 group within 16 cols
            int gm  = m0 + r;
            float4 v = make_float4(0.f, 0.f, 0.f, 0.f);
            if (gm < M) v = *(const float4*)(A + (long long)gm * 128 + kt + cg * 4);
            if (RELU_A) {
                v.x = fmaxf(v.x, 0.f); v.y = fmaxf(v.y, 0.f);
                v.z = fmaxf(v.z, 0.f); v.w = fmaxf(v.w, 0.f);
            }
            As[cg * 4 + 0][r] = v.x;
            As[cg * 4 + 1][r] = v.y;
            As[cg * 4 + 2][r] = v.z;
            As[cg * 4 + 3][r] = v.w;
        }
        // ---- load B tile (contiguous copy: rows kt..kt+15 of B)
        {
            const float4* bsrc = (const float4*)(B + kt * BN);
            float4* bdst = (float4*)(&Bs[0][0]);
#pragma unroll
            for (int idx = tid; idx < BK * BN / 4; idx += 256) bdst[idx] = bsrc[idx];
        }
        __syncthreads();
        // ---- compute
#pragma unroll
        for (int k = 0; k < BK; k++) {
            float a[8], b[TN];
            *(float4*)&a[0] = *(const float4*)&As[k][row];
            *(float4*)&a[4] = *(const float4*)&As[k][row + 4];
#pragma unroll
            for (int j = 0; j < TN; j += 4) *(float4*)&b[j] = *(const float4*)&Bs[k][col + j];
#pragma unroll
            for (int i = 0; i < 8; i++)
#pragma unroll
                for (int j = 0; j < TN; j++) acc[i][j] = fmaf(a[i], b[j], acc[i][j]);
        }
    }
    // ---- store
#pragma unroll
    for (int i = 0; i < 8; i++) {
        int gm = m0 + row + i;
        if (gm < M) {
#pragma unroll
            for (int j = 0; j < TN; j += 4)
                *(float4*)(C + (long long)gm * BN + col + j) = *(const float4*)&acc[i][j];
        }
    }
}

// ---------------- edge scatter: one warp per edge ------------------------------
// F=128: each lane handles one float4 of the feature row.
__global__ void scatter128_kernel(const int* __restrict__ src,
                                  const int* __restrict__ dst,
                                  const float* __restrict__ dis,
                                  const float* __restrict__ h,
                                  float* __restrict__ agg) {
    const int lane = threadIdx.x & 31;
    int warp = blockIdx.x * (blockDim.x >> 5) + (threadIdx.x >> 5);
    const int nwarps = gridDim.x * (blockDim.x >> 5);
    for (int e = warp; e < N_EDGES; e += nwarps) {
        int s = src[e];
        int d = dst[e];
        float nrm = dis[s] * dis[d];
        float4 v = ((const float4*)(h + (long long)s * 128))[lane];
        v.x *= nrm; v.y *= nrm; v.z *= nrm; v.w *= nrm;
        red_add_v4(agg + (long long)d * 128 + lane * 4, v);
    }
}

// F=64: each lane handles one float2.
__global__ void scatter64_kernel(const int* __restrict__ src,
                                 const int* __restrict__ dst,
                                 const float* __restrict__ dis,
                                 const float* __restrict__ h,
                                 float* __restrict__ agg) {
    const int lane = threadIdx.x & 31;
    int warp = blockIdx.x * (blockDim.x >> 5) + (threadIdx.x >> 5);
    const int nwarps = gridDim.x * (blockDim.x >> 5);
    for (int e = warp; e < N_EDGES; e += nwarps) {
        int s = src[e];
        int d = dst[e];
        float nrm = dis[s] * dis[d];
        float2 v = ((const float2*)(h + (long long)s * 64))[lane];
        v.x *= nrm; v.y *= nrm;
        red_add_v2(agg + (long long)d * 64 + lane * 2, v);
    }
}

// ---------------- launch --------------------------------------------------------
extern "C" void kernel_launch(void* const* d_in, const int* in_sizes, int n_in,
                              void* d_out, int out_size) {
    const float* x   = (const float*)d_in[0];
    const int*   ei  = (const int*)d_in[1];   // [2, E] int32 (JAX x64 disabled)
    const float* W1  = (const float*)d_in[2];
    const float* b1  = (const float*)d_in[3];
    const float* W2  = (const float*)d_in[4];
    const float* b2  = (const float*)d_in[5];
    float*       out = (float*)d_out;

    const int* src = ei;
    const int* dst = ei + N_EDGES;

    float* deg;  cudaGetSymbolAddress((void**)&deg,  g_deg);
    float* dis;  cudaGetSymbolAddress((void**)&dis,  g_dis);
    float* h1;   cudaGetSymbolAddress((void**)&h1,   g_h1);
    float* agg1; cudaGetSymbolAddress((void**)&agg1, g_agg1);
    float* h2;   cudaGetSymbolAddress((void**)&h2,   g_h2);

    // 1. degree + normalization
    zero_deg_kernel<<<(N_NODES + 255) / 256, 256>>>(deg);
    deg_kernel<<<(N_EDGES + 255) / 256, 256>>>(dst, deg);
    dis_kernel<<<(N_NODES + 255) / 256, 256>>>(deg, dis);

    // 2. h1 = x @ W1
    gemm128_kernel<128, 8, false><<<(N_NODES + 127) / 128, 256>>>(x, W1, h1, N_NODES);

    // 3. agg1 = b1 (broadcast), then scatter-add messages
    {
        long long total4 = (long long)N_NODES * HID_DIM / 4;
        init_bias_kernel<32><<<4096, 256>>>((float4*)agg1, b1, total4);
    }
    scatter128_kernel<<<4096, 256>>>(src, dst, dis, h1, agg1);

    // 4. h2 = relu(agg1) @ W2
    gemm128_kernel<64, 4, true><<<(N_NODES + 127) / 128, 256>>>(agg1, W2, h2, N_NODES);

    // 5. out = b2 (broadcast), then scatter-add messages
    {
        long long total4 = (long long)N_NODES * OUT_DIM / 4;
        init_bias_kernel<16><<<4096, 256>>>((float4*)out, b2, total4);
    }
    scatter64_kernel<<<4096, 256>>>(src, dst, dis, h2, out);
}

// round 3
// speedup vs baseline: 1.6702x; 1.6702x over previous
#include <cuda_runtime.h>

#define N_NODES 100000
#define N_EDGES 1600000
#define IN_DIM 128
#define HID_DIM 128
#define OUT_DIM 64

#define SCAN_TPB 512
#define SCAN_BLOCKS ((N_NODES + SCAN_TPB - 1) / SCAN_TPB)   // 196

// ---------------- device scratch ------------------------------------------------
__device__ int   g_deg[N_NODES];
__device__ int   g_rowptr[N_NODES + 1];
__device__ int   g_blocksum[SCAN_BLOCKS];
__device__ int   g_cursor[N_NODES];
__device__ int   g_csrc[N_EDGES];
__device__ float g_dis[N_NODES];
__device__ float g_h1[(size_t)N_NODES * HID_DIM];    // x @ W1
__device__ float g_agg1[(size_t)N_NODES * HID_DIM];  // relu(A_hat h1 + b1)
__device__ float g_h2[(size_t)N_NODES * OUT_DIM];    // agg1 @ W2

// ---------------- degree / norm -------------------------------------------------
__global__ void deg_kernel(const int* __restrict__ dst, int* __restrict__ deg) {
    int i = blockIdx.x * blockDim.x + threadIdx.x;
    if (i < N_EDGES) atomicAdd(&deg[dst[i]], 1);
}

__global__ void dis_kernel(const int* __restrict__ deg, float* __restrict__ dis) {
    int i = blockIdx.x * blockDim.x + threadIdx.x;
    if (i < N_NODES) {
        float d = (float)deg[i];
        dis[i] = (d > 0.0f) ? rsqrtf(d) : 0.0f;
    }
}

// ---------------- 3-pass exclusive scan -> rowptr -------------------------------
__global__ void scan_pass1(const int* __restrict__ deg, int* __restrict__ blocksum) {
    __shared__ int warpsum[SCAN_TPB / 32];
    int idx = blockIdx.x * SCAN_TPB + threadIdx.x;
    int v = (idx < N_NODES) ? deg[idx] : 0;
    // warp reduce
    for (int o = 16; o > 0; o >>= 1) v += __shfl_down_sync(0xffffffff, v, o);
    if ((threadIdx.x & 31) == 0) warpsum[threadIdx.x >> 5] = v;
    __syncthreads();
    if (threadIdx.x < SCAN_TPB / 32) {
        int s = warpsum[threadIdx.x];
        for (int o = 8; o > 0; o >>= 1) s += __shfl_down_sync(0xffff, s, o);
        if (threadIdx.x == 0) blocksum[blockIdx.x] = s;
    }
}

__global__ void scan_pass2(int* __restrict__ blocksum, int* __restrict__ rowptr) {
    if (threadIdx.x == 0) {
        int run = 0;
        for (int i = 0; i < SCAN_BLOCKS; i++) {
            int v = blocksum[i];
            blocksum[i] = run;      // exclusive
            run += v;
        }
        rowptr[N_NODES] = run;      // == N_EDGES
    }
}

__global__ void scan_pass3(const int* __restrict__ deg, const int* __restrict__ blocksum,
                           int* __restrict__ rowptr) {
    __shared__ int warpsum[SCAN_TPB / 32];
    int idx = blockIdx.x * SCAN_TPB + threadIdx.x;
    int lane = threadIdx.x & 31;
    int wid  = threadIdx.x >> 5;
    int v = (idx < N_NODES) ? deg[idx] : 0;
    // inclusive warp scan
    int sc = v;
    for (int o = 1; o < 32; o <<= 1) {
        int t = __shfl_up_sync(0xffffffff, sc, o);
        if (lane >= o) sc += t;
    }
    if (lane == 31) warpsum[wid] = sc;
    __syncthreads();
    if (wid == 0 && lane < SCAN_TPB / 32) {
        int s = warpsum[lane];
        int ss = s;
        for (int o = 1; o < SCAN_TPB / 32; o <<= 1) {
            int t = __shfl_up_sync(0xffff, ss, o);
            if (lane >= o) ss += t;
        }
        warpsum[lane] = ss - s;     // exclusive warp offsets
    }
    __syncthreads();
    if (idx < N_NODES)
        rowptr[idx] = blocksum[blockIdx.x] + warpsum[wid] + (sc - v);  // exclusive
}

// ---------------- CSR fill -------------------------------------------------------
__global__ void fill_kernel(const int* __restrict__ src, const int* __restrict__ dst,
                            const int* __restrict__ rowptr, int* __restrict__ cursor,
                            int* __restrict__ csrc) {
    int e = blockIdx.x * blockDim.x + threadIdx.x;
    if (e < N_EDGES) {
        int d = dst[e];
        int pos = rowptr[d] + atomicAdd(&cursor[d], 1);
        csrc[pos] = src[e];
    }
}

// ---------------- SGEMM: C[M,BN] = A[M,128] @ B[128,BN] --------------------------
template<int BN, int TN>
__global__ void __launch_bounds__(256) gemm128_kernel(const float* __restrict__ A,
                                                      const float* __restrict__ B,
                                                      float* __restrict__ C, int M) {
    constexpr int BM = 128;
    constexpr int BK = 16;
    __shared__ float As[BK][BM];
    __shared__ float Bs[BK][BN];

    const int tid = threadIdx.x;
    const int m0 = blockIdx.x * BM;
    const int tx = tid & 15;
    const int ty = tid >> 4;
    const int row = ty * 8;
    const int col = tx * TN;

    float acc[8][TN];
#pragma unroll
    for (int i = 0; i < 8; i++)
#pragma unroll
        for (int j = 0; j < TN; j++) acc[i][j] = 0.0f;

    for (int kt = 0; kt < 128; kt += BK) {
        __syncthreads();
#pragma unroll
        for (int it = 0; it < 2; it++) {
            int idx = tid + it * 256;
            int r   = idx >> 2;
            int cg  = idx & 3;
            int gm  = m0 + r;
            float4 v = make_float4(0.f, 0.f, 0.f, 0.f);
            if (gm < M) v = *(const float4*)(A + (long long)gm * 128 + kt + cg * 4);
            As[cg * 4 + 0][r] = v.x;
            As[cg * 4 + 1][r] = v.y;
            As[cg * 4 + 2][r] = v.z;
            As[cg * 4 + 3][r] = v.w;
        }
        {
            const float4* bsrc = (const float4*)(B + kt * BN);
            float4* bdst = (float4*)(&Bs[0][0]);
#pragma unroll
            for (int idx = tid; idx < BK * BN / 4; idx += 256) bdst[idx] = bsrc[idx];
        }
        __syncthreads();
#pragma unroll
        for (int k = 0; k < BK; k++) {
            float a[8], b[TN];
            *(float4*)&a[0] = *(const float4*)&As[k][row];
            *(float4*)&a[4] = *(const float4*)&As[k][row + 4];
#pragma unroll
            for (int j = 0; j < TN; j += 4) *(float4*)&b[j] = *(const float4*)&Bs[k][col + j];
#pragma unroll
            for (int i = 0; i < 8; i++)
#pragma unroll
                for (int j = 0; j < TN; j++) acc[i][j] = fmaf(a[i], b[j], acc[i][j]);
        }
    }
#pragma unroll
    for (int i = 0; i < 8; i++) {
        int gm = m0 + row + i;
        if (gm < M) {
#pragma unroll
            for (int j = 0; j < TN; j += 4)
                *(float4*)(C + (long long)gm * BN + col + j) = *(const float4*)&acc[i][j];
        }
    }
}

// ---------------- CSR gather: one warp per node ----------------------------------
// F=128: lane owns one float4.  out = relu_opt( dis[n] * sum_e dis[s]*h[s] + bias )
template<bool RELU>
__global__ void gather128_kernel(const int* __restrict__ rowptr,
                                 const int* __restrict__ csrc,
                                 const float* __restrict__ dis,
                                 const float* __restrict__ h,
                                 const float* __restrict__ bias,
                                 float* __restrict__ out) {
    const int lane = threadIdx.x & 31;
    const int node = blockIdx.x * (blockDim.x >> 5) + (threadIdx.x >> 5);
    if (node >= N_NODES) return;

    const int start = rowptr[node];
    const int end   = rowptr[node + 1];
    float4 acc = make_float4(0.f, 0.f, 0.f, 0.f);

    int j = start;
    for (; j + 2 <= end; j += 2) {
        int s0 = csrc[j], s1 = csrc[j + 1];
        float w0 = dis[s0], w1 = dis[s1];
        float4 v0 = ((const float4*)(h + (long long)s0 * 128))[lane];
        float4 v1 = ((const float4*)(h + (long long)s1 * 128))[lane];
        acc.x += w0 * v0.x + w1 * v1.x;
        acc.y += w0 * v0.y + w1 * v1.y;
        acc.z += w0 * v0.z + w1 * v1.z;
        acc.w += w0 * v0.w + w1 * v1.w;
    }
    if (j < end) {
        int s0 = csrc[j];
        float w0 = dis[s0];
        float4 v0 = ((const float4*)(h + (long long)s0 * 128))[lane];
        acc.x += w0 * v0.x; acc.y += w0 * v0.y; acc.z += w0 * v0.z; acc.w += w0 * v0.w;
    }

    float dn = dis[node];
    float4 bv = ((const float4*)bias)[lane];
    float4 r;
    r.x = dn * acc.x + bv.x;
    r.y = dn * acc.y + bv.y;
    r.z = dn * acc.z + bv.z;
    r.w = dn * acc.w + bv.w;
    if (RELU) {
        r.x = fmaxf(r.x, 0.f); r.y = fmaxf(r.y, 0.f);
        r.z = fmaxf(r.z, 0.f); r.w = fmaxf(r.w, 0.f);
    }
    ((float4*)(out + (long long)node * 128))[lane] = r;
}

// F=64: lane owns one float2.
__global__ void gather64_kernel(const int* __restrict__ rowptr,
                                const int* __restrict__ csrc,
                                const float* __restrict__ dis,
                                const float* __restrict__ h,
                                const float* __restrict__ bias,
                                float* __restrict__ out) {
    const int lane = threadIdx.x & 31;
    const int node = blockIdx.x * (blockDim.x >> 5) + (threadIdx.x >> 5);
    if (node >= N_NODES) return;

    const int start = rowptr[node];
    const int end   = rowptr[node + 1];
    float2 acc = make_float2(0.f, 0.f);

    int j = start;
    for (; j + 2 <= end; j += 2) {
        int s0 = csrc[j], s1 = csrc[j + 1];
        float w0 = dis[s0], w1 = dis[s1];
        float2 v0 = ((const float2*)(h + (long long)s0 * 64))[lane];
        float2 v1 = ((const float2*)(h + (long long)s1 * 64))[lane];
        acc.x += w0 * v0.x + w1 * v1.x;
        acc.y += w0 * v0.y + w1 * v1.y;
    }
    if (j < end) {
        int s0 = csrc[j];
        float w0 = dis[s0];
        float2 v0 = ((const float2*)(h + (long long)s0 * 64))[lane];
        acc.x += w0 * v0.x; acc.y += w0 * v0.y;
    }

    float dn = dis[node];
    float2 bv = ((const float2*)bias)[lane];
    float2 r;
    r.x = dn * acc.x + bv.x;
    r.y = dn * acc.y + bv.y;
    ((float2*)(out + (long long)node * 64))[lane] = r;
}

// ---------------- launch ----------------------------------------------------------
extern "C" void kernel_launch(void* const* d_in, const int* in_sizes, int n_in,
                              void* d_out, int out_size) {
    const float* x   = (const float*)d_in[0];
    const int*   ei  = (const int*)d_in[1];   // [2, E] int32
    const float* W1  = (const float*)d_in[2];
    const float* b1  = (const float*)d_in[3];
    const float* W2  = (const float*)d_in[4];
    const float* b2  = (const float*)d_in[5];
    float*       out = (float*)d_out;

    const int* src = ei;
    const int* dst = ei + N_EDGES;

    int*   deg;      cudaGetSymbolAddress((void**)&deg,      g_deg);
    int*   rowptr;   cudaGetSymbolAddress((void**)&rowptr,   g_rowptr);
    int*   blocksum; cudaGetSymbolAddress((void**)&blocksum, g_blocksum);
    int*   cursor;   cudaGetSymbolAddress((void**)&cursor,   g_cursor);
    int*   csrc;     cudaGetSymbolAddress((void**)&csrc,     g_csrc);
    float* dis;      cudaGetSymbolAddress((void**)&dis,      g_dis);
    float* h1;       cudaGetSymbolAddress((void**)&h1,       g_h1);
    float* agg1;     cudaGetSymbolAddress((void**)&agg1,     g_agg1);
    float* h2;       cudaGetSymbolAddress((void**)&h2,       g_h2);

    // --- CSR build ---
    cudaMemsetAsync(deg, 0, N_NODES * sizeof(int));
    cudaMemsetAsync(cursor, 0, N_NODES * sizeof(int));
    deg_kernel<<<(N_EDGES + 255) / 256, 256>>>(dst, deg);
    dis_kernel<<<(N_NODES + 255) / 256, 256>>>(deg, dis);
    scan_pass1<<<SCAN_BLOCKS, SCAN_TPB>>>(deg, blocksum);
    scan_pass2<<<1, 32>>>(blocksum, rowptr);
    scan_pass3<<<SCAN_BLOCKS, SCAN_TPB>>>(deg, blocksum, rowptr);
    fill_kernel<<<(N_EDGES + 255) / 256, 256>>>(src, dst, rowptr, cursor, csrc);

    // --- layer 1: h1 = x @ W1 ; agg1 = relu(D^-1/2 A D^-1/2 h1 + b1) ---
    gemm128_kernel<128, 8><<<(N_NODES + 127) / 128, 256>>>(x, W1, h1, N_NODES);
    gather128_kernel<true><<<(N_NODES + 7) / 8, 256>>>(rowptr, csrc, dis, h1, b1, agg1);

    // --- layer 2: h2 = agg1 @ W2 ; out = D^-1/2 A D^-1/2 h2 + b2 ---
    gemm128_kernel<64, 4><<<(N_NODES + 127) / 128, 256>>>(agg1, W2, h2, N_NODES);
    gather64_kernel<<<(N_NODES + 7) / 8, 256>>>(rowptr, csrc, dis, h2, b2, out);
}